// round 13
// baseline (speedup 1.0000x reference)
#include <cuda_runtime.h>
#include <cuda_bf16.h>
#include <cstdint>
#include <cstddef>

#define NN 100000
#define EE 1000000
#define DD 64
#define KK 8
#define LL 3

#define SCAN_TPB 1024
#define SCAN_BLOCKS ((NN + SCAN_TPB - 1) / SCAN_TPB)   // 98
#define NBINS 64
#define EPAD (EE + 7 * NN + 64)     // rows padded to multiples of 8 edges

// ---------------- device scratch ----------------
__device__ float g_T[7][(size_t)NN * DD];
__device__ float g_out1[(size_t)NN * DD];
__device__ float g_out2[(size_t)NN * DD];
__device__ float g_xp[(size_t)NN * DD];
__device__ float g_deg[NN];
__device__ float g_dinv[NN];
__device__ int   g_cnt[NN];
__device__ int   g_cnt8[NN];        // padded in-degree by permuted id
__device__ int   g_rowstart[NN + 1];
__device__ int   g_cursor[NN];
__device__ int   g_bsum[SCAN_BLOCKS + 32];
__device__ int   g_dbins[NBINS];
__device__ int   g_dcur[NBINS];
__device__ int   g_perm[NN];
__device__ int   g_rank[NN];
__device__ __align__(16) float2 g_adj[EPAD];   // pads are zeroed => src=0, w=0
// W pre-converted per (l,k) slice: 4096 bf16 hi then 4096 bf16 lo, layout [n][kk].
__device__ __align__(16) __nv_bfloat16 g_Wc[LL * KK * 2 * DD * DD];

// ---------------- normalization / CSR / sort ----------------
__global__ void deg_hist_kernel(const int* __restrict__ src, const int* __restrict__ dst,
                                const float* __restrict__ w,
                                float* __restrict__ deg, int* __restrict__ cnt) {
    int e = blockIdx.x * blockDim.x + threadIdx.x;
    if (e >= EE) return;
    int s = src[e], d = dst[e];
    float ww = (s == d) ? 0.0f : w[e];
    if (ww != 0.0f) atomicAdd(&deg[s], ww);
    atomicAdd(&cnt[d], 1);
}

__global__ void dinv_binhist_kernel(const float* __restrict__ deg, const int* __restrict__ cnt,
                                    float* __restrict__ dinv, int* __restrict__ dbins) {
    int i = blockIdx.x * blockDim.x + threadIdx.x;
    if (i >= NN) return;
    float d = deg[i];
    dinv[i] = (d > 0.0f) ? rsqrtf(d) : 0.0f;
    atomicAdd(&dbins[min(cnt[i], NBINS - 1)], 1);
}

__global__ void bin_scan_kernel(const int* __restrict__ dbins, int* __restrict__ dcur) {
    __shared__ int s[NBINS];
    int t = threadIdx.x;
    int v = dbins[t];
    s[t] = v;
    __syncthreads();
#pragma unroll
    for (int off = 1; off < NBINS; off <<= 1) {
        int tt = (t >= off) ? s[t - off] : 0;
        __syncthreads();
        s[t] += tt;
        __syncthreads();
    }
    dcur[t] = s[t] - v;
}

// block-aggregated scatter: smem histogram, one global atomic per bin per block
__global__ __launch_bounds__(256)
void bin_scatter_kernel(const int* __restrict__ cnt, int* __restrict__ dcur,
                        int* __restrict__ perm, int* __restrict__ rank,
                        int* __restrict__ cnt8) {
    __shared__ int localCnt[NBINS];
    __shared__ int localBase[NBINS];
    int tid = threadIdx.x;
    if (tid < NBINS) localCnt[tid] = 0;
    __syncthreads();
    int i = blockIdx.x * blockDim.x + tid;
    int c = 0, b = 0, lpos = 0;
    bool valid = (i < NN);
    if (valid) {
        c = cnt[i];
        b = min(c, NBINS - 1);
        lpos = atomicAdd(&localCnt[b], 1);
    }
    __syncthreads();
    if (tid < NBINS && localCnt[tid] > 0)
        localBase[tid] = atomicAdd(&dcur[tid], localCnt[tid]);
    __syncthreads();
    if (valid) {
        int pos = localBase[b] + lpos;
        perm[pos] = i;
        rank[i] = pos;
        cnt8[pos] = (c + 7) & ~7;     // pad rows to multiples of 8
    }
}

__global__ void permute_x_kernel(const float* __restrict__ x, const int* __restrict__ perm,
                                 float* __restrict__ xp) {
    unsigned tid = blockIdx.x * blockDim.x + threadIdx.x;
    unsigned g = tid >> 4;
    if (g >= NN) return;
    unsigned lane = tid & 15u;
    int n = perm[g];
    reinterpret_cast<float4*>(xp)[(size_t)g * 16 + lane] =
        reinterpret_cast<const float4*>(x)[(size_t)n * 16 + lane];
}

__global__ void scan_block_kernel(const int* __restrict__ cnt, int* __restrict__ rowstart,
                                  int* __restrict__ bsum) {
    __shared__ int s[SCAN_TPB];
    int i = blockIdx.x * SCAN_TPB + threadIdx.x;
    int v = (i < NN) ? cnt[i] : 0;
    s[threadIdx.x] = v;
    __syncthreads();
#pragma unroll
    for (int off = 1; off < SCAN_TPB; off <<= 1) {
        int t = (threadIdx.x >= off) ? s[threadIdx.x - off] : 0;
        __syncthreads();
        s[threadIdx.x] += t;
        __syncthreads();
    }
    if (i <= NN) rowstart[i] = s[threadIdx.x] - v;
    if (threadIdx.x == SCAN_TPB - 1) bsum[blockIdx.x] = s[threadIdx.x];
}

__global__ void scan_sums_kernel(int* __restrict__ bsum) {
    __shared__ int s[128];
    int t = threadIdx.x;
    int v = (t < SCAN_BLOCKS) ? bsum[t] : 0;
    s[t] = v;
    __syncthreads();
#pragma unroll
    for (int off = 1; off < 128; off <<= 1) {
        int tt = (t >= off) ? s[t - off] : 0;
        __syncthreads();
        s[t] += tt;
        __syncthreads();
    }
    if (t < SCAN_BLOCKS) bsum[t] = s[t] - v;
}

__global__ void scan_add_kernel(int* __restrict__ rowstart, const int* __restrict__ bsum,
                                int* __restrict__ cursor) {
    int i = blockIdx.x * blockDim.x + threadIdx.x;
    if (i > NN) return;
    int r = rowstart[i] + bsum[i / SCAN_TPB];
    rowstart[i] = r;
    if (i < NN) cursor[i] = r;
}

__global__ void scatter_kernel(const int* __restrict__ src, const int* __restrict__ dst,
                               const float* __restrict__ w, const float* __restrict__ dinv,
                               const int* __restrict__ rank,
                               int* __restrict__ cursor, float2* __restrict__ adj) {
    int e = blockIdx.x * blockDim.x + threadIdx.x;
    if (e >= EE) return;
    int s = src[e], d = dst[e];
    float ww = (s == d) ? 0.0f : w[e];
    float nrm = -dinv[s] * ww * dinv[d];
    int pos = atomicAdd(&cursor[rank[d]], 1);
    adj[pos] = make_float2(__int_as_float(rank[s]), nrm);
}

// W conversion: per slice, hi[n][kk] then lo[n][kk] (bf16). B[n][kk] = W[kk][n].
__global__ void convw_kernel(const float* __restrict__ Wt, __nv_bfloat16* __restrict__ Wc) {
    int idx = blockIdx.x * blockDim.x + threadIdx.x;
    if (idx >= LL * KK * DD * DD) return;
    int n = idx & 63;
    int kk = (idx >> 6) & 63;
    int slice = idx >> 12;
    float w = Wt[(size_t)slice * 4096 + kk * 64 + n];
    __nv_bfloat16 hi = __float2bfloat16(w);
    __nv_bfloat16 lo = __float2bfloat16(w - __bfloat162float(hi));
    __nv_bfloat16* base = Wc + (size_t)slice * 8192;
    base[n * 64 + kk] = hi;
    base[4096 + n * 64 + kk] = lo;
}

// ---------------- CSR gather propagation (8-padded rows, pipelined adj) ----------------
template <bool FIRST>
__global__ __launch_bounds__(256)
void prop16_kernel(const float* __restrict__ h, const float2* __restrict__ adj,
                   const int* __restrict__ rowstart, const float* __restrict__ t0,
                   float* __restrict__ out) {
    unsigned tid = blockIdx.x * blockDim.x + threadIdx.x;
    unsigned n = tid >> 4;
    if (n >= NN) return;
    unsigned lane = tid & 15u;
    int r0 = rowstart[n];
    int r1 = rowstart[n + 1];        // both multiples of 8

    float4 acc = make_float4(0.f, 0.f, 0.f, 0.f);
    const float4* hb = reinterpret_cast<const float4*>(h);
    const float4* av = reinterpret_cast<const float4*>(adj);   // 2 edges per float4

    int c = r0 >> 1;
    int cend = r1 >> 1;
    if (c < cend) {
        float4 q0 = __ldg(&av[c]);
        float4 q1 = __ldg(&av[c + 1]);
        float4 q2 = __ldg(&av[c + 2]);
        float4 q3 = __ldg(&av[c + 3]);
#pragma unroll 1
        for (;;) {
            // issue all 8 h-loads for the current chunk
            float4 v0 = hb[(size_t)__float_as_int(q0.x) * 16 + lane];
            float4 v1 = hb[(size_t)__float_as_int(q0.z) * 16 + lane];
            float4 v2 = hb[(size_t)__float_as_int(q1.x) * 16 + lane];
            float4 v3 = hb[(size_t)__float_as_int(q1.z) * 16 + lane];
            float4 v4 = hb[(size_t)__float_as_int(q2.x) * 16 + lane];
            float4 v5 = hb[(size_t)__float_as_int(q2.z) * 16 + lane];
            float4 v6 = hb[(size_t)__float_as_int(q3.x) * 16 + lane];
            float4 v7 = hb[(size_t)__float_as_int(q3.z) * 16 + lane];
            float w0 = q0.y, w1 = q0.w, w2 = q1.y, w3 = q1.w;
            float w4 = q2.y, w5 = q2.w, w6 = q3.y, w7 = q3.w;
            c += 4;
            bool more = (c < cend);
            if (more) {               // prefetch next chunk's adj under the h latency
                q0 = __ldg(&av[c]);
                q1 = __ldg(&av[c + 1]);
                q2 = __ldg(&av[c + 2]);
                q3 = __ldg(&av[c + 3]);
            }
            acc.x = fmaf(w0, v0.x, acc.x); acc.y = fmaf(w0, v0.y, acc.y);
            acc.z = fmaf(w0, v0.z, acc.z); acc.w = fmaf(w0, v0.w, acc.w);
            acc.x = fmaf(w1, v1.x, acc.x); acc.y = fmaf(w1, v1.y, acc.y);
            acc.z = fmaf(w1, v1.z, acc.z); acc.w = fmaf(w1, v1.w, acc.w);
            acc.x = fmaf(w2, v2.x, acc.x); acc.y = fmaf(w2, v2.y, acc.y);
            acc.z = fmaf(w2, v2.z, acc.z); acc.w = fmaf(w2, v2.w, acc.w);
            acc.x = fmaf(w3, v3.x, acc.x); acc.y = fmaf(w3, v3.y, acc.y);
            acc.z = fmaf(w3, v3.z, acc.z); acc.w = fmaf(w3, v3.w, acc.w);
            acc.x = fmaf(w4, v4.x, acc.x); acc.y = fmaf(w4, v4.y, acc.y);
            acc.z = fmaf(w4, v4.z, acc.z); acc.w = fmaf(w4, v4.w, acc.w);
            acc.x = fmaf(w5, v5.x, acc.x); acc.y = fmaf(w5, v5.y, acc.y);
            acc.z = fmaf(w5, v5.z, acc.z); acc.w = fmaf(w5, v5.w, acc.w);
            acc.x = fmaf(w6, v6.x, acc.x); acc.y = fmaf(w6, v6.y, acc.y);
            acc.z = fmaf(w6, v6.z, acc.z); acc.w = fmaf(w6, v6.w, acc.w);
            acc.x = fmaf(w7, v7.x, acc.x); acc.y = fmaf(w7, v7.y, acc.y);
            acc.z = fmaf(w7, v7.z, acc.z); acc.w = fmaf(w7, v7.w, acc.w);
            if (!more) break;
        }
    }

    size_t idx = (size_t)n * 16 + lane;
    if (FIRST) {
        reinterpret_cast<float4*>(out)[idx] = acc;
    } else {
        float4 t = reinterpret_cast<const float4*>(t0)[idx];
        reinterpret_cast<float4*>(out)[idx] =
            make_float4(2.0f * acc.x - t.x, 2.0f * acc.y - t.y,
                        2.0f * acc.z - t.z, 2.0f * acc.w - t.w);
    }
}

// ---------------- mma.sync bf16 hi/lo-split GEMM + bias + relu (r11-proven) ----------------
struct TPtrs { const float* p[KK]; };

#define PADROW 144               // 72 bf16 = 144 bytes per smem row
#define SM_XHI  0                // [128][72] bf16
#define SM_XLO  18432
#define SM_WHI  36864            // [64][72] bf16
#define SM_WLO  46080
#define SM_TOTAL 55296

#define MMA_BF16(c, a0, a1, a2, a3, b0, b1) \
    asm volatile("mma.sync.aligned.m16n8k16.row.col.f32.bf16.bf16.f32 " \
                 "{%0,%1,%2,%3}, {%4,%5,%6,%7}, {%8,%9}, {%0,%1,%2,%3};" \
                 : "+f"((c)[0]), "+f"((c)[1]), "+f"((c)[2]), "+f"((c)[3]) \
                 : "r"(a0), "r"(a1), "r"(a2), "r"(a3), "r"(b0), "r"(b1))

__global__ __launch_bounds__(256)
void gemm_mma_kernel(TPtrs ts, const __nv_bfloat16* __restrict__ Wc_layer,
                     const float* __restrict__ bias, float* __restrict__ out,
                     const int* __restrict__ operm) {
    extern __shared__ __align__(16) char smem[];
    int tid = threadIdx.x;
    int w = tid >> 5;
    int lane = tid & 31;
    int gid = lane >> 2;
    int tig = lane & 3;
    int row0 = blockIdx.x * 128;
    int rA = w * 16 + gid;

    float acc[8][4];
#pragma unroll
    for (int nt = 0; nt < 8; nt++)
#pragma unroll
        for (int c = 0; c < 4; c++) acc[nt][c] = 0.0f;

    for (int s = 0; s < KK; ++s) {
        if (s > 0) __syncthreads();

        const float4* Xv = reinterpret_cast<const float4*>(ts.p[s]);
#pragma unroll
        for (int i = 0; i < 8; i++) {
            int idx = tid + i * 256;
            int r = idx >> 4, c4 = idx & 15;
            int gr = row0 + r;
            float4 v = make_float4(0.f, 0.f, 0.f, 0.f);
            if (gr < NN) v = Xv[(size_t)gr * 16 + c4];
            __nv_bfloat162 h01 = __floats2bfloat162_rn(v.x, v.y);
            __nv_bfloat162 h23 = __floats2bfloat162_rn(v.z, v.w);
            float2 f01 = __bfloat1622float2(h01);
            float2 f23 = __bfloat1622float2(h23);
            __nv_bfloat162 l01 = __floats2bfloat162_rn(v.x - f01.x, v.y - f01.y);
            __nv_bfloat162 l23 = __floats2bfloat162_rn(v.z - f23.x, v.w - f23.y);
            uint32_t off = (uint32_t)r * PADROW + (uint32_t)c4 * 8;
            *reinterpret_cast<__nv_bfloat162*>(smem + SM_XHI + off) = h01;
            *reinterpret_cast<__nv_bfloat162*>(smem + SM_XHI + off + 4) = h23;
            *reinterpret_cast<__nv_bfloat162*>(smem + SM_XLO + off) = l01;
            *reinterpret_cast<__nv_bfloat162*>(smem + SM_XLO + off + 4) = l23;
        }
        const uint2* Wg = reinterpret_cast<const uint2*>(Wc_layer) + (size_t)s * 2048;
#pragma unroll
        for (int i = 0; i < 8; i++) {
            int idx = tid + i * 256;
            int half = idx >> 10;
            int j = idx & 1023;
            int n = j >> 4, c = j & 15;
            uint2 val = Wg[idx];
            *reinterpret_cast<uint2*>(smem + (half ? SM_WLO : SM_WHI)
                                      + (uint32_t)n * PADROW + (uint32_t)c * 8) = val;
        }
        __syncthreads();

#pragma unroll
        for (int kstep = 0; kstep < 4; kstep++) {
            uint32_t acol = (uint32_t)(kstep * 16 + 2 * tig) * 2;
            const char* axh = smem + SM_XHI + (uint32_t)rA * PADROW + acol;
            const char* axl = smem + SM_XLO + (uint32_t)rA * PADROW + acol;
            uint32_t ah0 = *reinterpret_cast<const uint32_t*>(axh);
            uint32_t ah1 = *reinterpret_cast<const uint32_t*>(axh + 8 * PADROW);
            uint32_t ah2 = *reinterpret_cast<const uint32_t*>(axh + 16);
            uint32_t ah3 = *reinterpret_cast<const uint32_t*>(axh + 8 * PADROW + 16);
            uint32_t al0 = *reinterpret_cast<const uint32_t*>(axl);
            uint32_t al1 = *reinterpret_cast<const uint32_t*>(axl + 8 * PADROW);
            uint32_t al2 = *reinterpret_cast<const uint32_t*>(axl + 16);
            uint32_t al3 = *reinterpret_cast<const uint32_t*>(axl + 8 * PADROW + 16);
#pragma unroll
            for (int nt = 0; nt < 8; nt++) {
                uint32_t boff = (uint32_t)(nt * 8 + gid) * PADROW + acol;
                uint32_t bh0 = *reinterpret_cast<const uint32_t*>(smem + SM_WHI + boff);
                uint32_t bh1 = *reinterpret_cast<const uint32_t*>(smem + SM_WHI + boff + 16);
                uint32_t bl0 = *reinterpret_cast<const uint32_t*>(smem + SM_WLO + boff);
                uint32_t bl1 = *reinterpret_cast<const uint32_t*>(smem + SM_WLO + boff + 16);
                MMA_BF16(acc[nt], ah0, ah1, ah2, ah3, bh0, bh1);
                MMA_BF16(acc[nt], al0, al1, al2, al3, bh0, bh1);
                MMA_BF16(acc[nt], ah0, ah1, ah2, ah3, bl0, bl1);
            }
        }
    }

    int gr1 = row0 + rA;
    int gr2 = gr1 + 8;
    int or1 = (gr1 < NN) ? (operm ? operm[gr1] : gr1) : -1;
    int or2 = (gr2 < NN) ? (operm ? operm[gr2] : gr2) : -1;
#pragma unroll
    for (int nt = 0; nt < 8; nt++) {
        int col = nt * 8 + 2 * tig;
        float b0 = bias[col], b1 = bias[col + 1];
        if (or1 >= 0) {
            float2 v;
            v.x = fmaxf(acc[nt][0] + b0, 0.f);
            v.y = fmaxf(acc[nt][1] + b1, 0.f);
            *reinterpret_cast<float2*>(out + (size_t)or1 * DD + col) = v;
        }
        if (or2 >= 0) {
            float2 v;
            v.x = fmaxf(acc[nt][2] + b0, 0.f);
            v.y = fmaxf(acc[nt][3] + b1, 0.f);
            *reinterpret_cast<float2*>(out + (size_t)or2 * DD + col) = v;
        }
    }
}

// ---------------- launcher ----------------
extern "C" void kernel_launch(void* const* d_in, const int* in_sizes, int n_in,
                              void* d_out, int out_size) {
    const float* x  = (const float*)d_in[0];
    const int*   ei = (const int*)d_in[1];
    const float* ew = (const float*)d_in[2];
    const float* Wt = (const float*)d_in[3];
    const float* Bs = (const float*)d_in[4];
    const int* src = ei;
    const int* dst = ei + EE;

    float *Tbuf, *out1, *out2, *xp, *deg, *dinv;
    int *cnt, *cnt8, *rowstart, *cursor, *bsum, *dbins, *dcur, *perm, *rank;
    float2* adj;
    __nv_bfloat16* Wc;
    cudaGetSymbolAddress((void**)&Tbuf, g_T);
    cudaGetSymbolAddress((void**)&out1, g_out1);
    cudaGetSymbolAddress((void**)&out2, g_out2);
    cudaGetSymbolAddress((void**)&xp, g_xp);
    cudaGetSymbolAddress((void**)&deg, g_deg);
    cudaGetSymbolAddress((void**)&dinv, g_dinv);
    cudaGetSymbolAddress((void**)&cnt, g_cnt);
    cudaGetSymbolAddress((void**)&cnt8, g_cnt8);
    cudaGetSymbolAddress((void**)&rowstart, g_rowstart);
    cudaGetSymbolAddress((void**)&cursor, g_cursor);
    cudaGetSymbolAddress((void**)&bsum, g_bsum);
    cudaGetSymbolAddress((void**)&dbins, g_dbins);
    cudaGetSymbolAddress((void**)&dcur, g_dcur);
    cudaGetSymbolAddress((void**)&perm, g_perm);
    cudaGetSymbolAddress((void**)&rank, g_rank);
    cudaGetSymbolAddress((void**)&adj, g_adj);
    cudaGetSymbolAddress((void**)&Wc, g_Wc);

    static int smem_set = 0;
    if (!smem_set) {
        cudaFuncSetAttribute(gemm_mma_kernel,
                             cudaFuncAttributeMaxDynamicSharedMemorySize, SM_TOTAL);
        smem_set = 1;
    }

    const size_t FB = (size_t)NN * DD;
    float* TB[7];
    for (int i = 0; i < 7; i++) TB[i] = Tbuf + (size_t)i * FB;

    const int T = 256;
    const int edgeBlocks = (EE + T - 1) / T;
    const int nodeBlocks = (NN + T - 1) / T;
    const int node1Blocks = (NN + 1 + T - 1) / T;
    const int propBlocks = (NN * 16 + T - 1) / T;
    const int gemmBlocks = (NN + 127) / 128;
    const int convwBlocks = (LL * KK * DD * DD + T - 1) / T;

    // --- setup ---
    cudaMemsetAsync(deg, 0, NN * sizeof(float));
    cudaMemsetAsync(cnt, 0, NN * sizeof(int));
    cudaMemsetAsync(dbins, 0, NBINS * sizeof(int));
    cudaMemsetAsync(adj, 0, (size_t)EPAD * sizeof(float2));   // pads: src=0, w=0
    deg_hist_kernel<<<edgeBlocks, T>>>(src, dst, ew, deg, cnt);
    dinv_binhist_kernel<<<nodeBlocks, T>>>(deg, cnt, dinv, dbins);
    bin_scan_kernel<<<1, NBINS>>>(dbins, dcur);
    bin_scatter_kernel<<<nodeBlocks, T>>>(cnt, dcur, perm, rank, cnt8);
    scan_block_kernel<<<SCAN_BLOCKS, SCAN_TPB>>>(cnt8, rowstart, bsum);
    scan_sums_kernel<<<1, 128>>>(bsum);
    scan_add_kernel<<<node1Blocks, T>>>(rowstart, bsum, cursor);
    scatter_kernel<<<edgeBlocks, T>>>(src, dst, ew, dinv, rank, cursor, adj);
    permute_x_kernel<<<propBlocks, T>>>(x, perm, xp);
    convw_kernel<<<convwBlocks, T>>>(Wt, Wc);

    // --- layers ---
    const float* hin = xp;
    float* houts[3] = {out1, out2, (float*)d_out};

    for (int l = 0; l < LL; l++) {
        prop16_kernel<true><<<propBlocks, T>>>(hin, adj, rowstart, nullptr, TB[0]);
        for (int k = 2; k < KK; k++) {
            const float* tin = TB[k - 2];
            const float* t0 = (k == 2) ? hin : TB[k - 3];
            prop16_kernel<false><<<propBlocks, T>>>(tin, adj, rowstart, t0, TB[k - 1]);
        }
        TPtrs tsp;
        tsp.p[0] = hin;
        for (int k = 1; k < KK; k++) tsp.p[k] = TB[k - 1];
        const int* operm = (l == LL - 1) ? perm : nullptr;
        gemm_mma_kernel<<<gemmBlocks, 256, SM_TOTAL>>>(
            tsp, Wc + (size_t)l * KK * 2 * DD * DD, Bs + (size_t)l * DD,
            houts[l], operm);
        hin = houts[l];
    }
}

// round 14
// speedup vs baseline: 1.0607x; 1.0607x over previous
#include <cuda_runtime.h>
#include <cuda_bf16.h>
#include <cstdint>
#include <cstddef>

#define NN 100000
#define EE 1000000
#define DD 64
#define KK 8
#define LL 3
#define NBINS 64

// ---------------- device scratch ----------------
__device__ float g_T[7][(size_t)NN * DD];
__device__ float g_out1[(size_t)NN * DD];
__device__ float g_out2[(size_t)NN * DD];
__device__ float g_xp[(size_t)NN * DD];
__device__ float g_deg[NN];
__device__ float g_dinv[NN];
__device__ int   g_cnt[NN];
__device__ int   g_rowstart[NN];
__device__ int   g_rowlen[NN];
__device__ int   g_cursor[NN];
__device__ int   g_dbins[NBINS];     // node count per degree bin
__device__ int   g_ebins[NBINS];     // edge count per degree bin
__device__ int   g_dcur[NBINS];      // node cursor per bin
__device__ int   g_ecur[NBINS];      // edge cursor per bin
__device__ int   g_perm[NN];
__device__ int   g_rank[NN];
__device__ float2 g_adj[EE];
// W pre-converted per (l,k) slice: 4096 bf16 hi then 4096 bf16 lo, layout [n][kk].
__device__ __align__(16) __nv_bfloat16 g_Wc[LL * KK * 2 * DD * DD];

// ---------------- normalization / CSR / sort ----------------
__global__ void deg_hist_kernel(const int* __restrict__ src, const int* __restrict__ dst,
                                const float* __restrict__ w,
                                float* __restrict__ deg, int* __restrict__ cnt) {
    int e = blockIdx.x * blockDim.x + threadIdx.x;
    if (e >= EE) return;
    int s = src[e], d = dst[e];
    float ww = (s == d) ? 0.0f : w[e];
    if (ww != 0.0f) atomicAdd(&deg[s], ww);
    atomicAdd(&cnt[d], 1);
}

// fused: dinv + node/edge histograms per degree bin
__global__ void dinv_binhist_kernel(const float* __restrict__ deg, const int* __restrict__ cnt,
                                    float* __restrict__ dinv,
                                    int* __restrict__ dbins, int* __restrict__ ebins) {
    int i = blockIdx.x * blockDim.x + threadIdx.x;
    if (i >= NN) return;
    float d = deg[i];
    dinv[i] = (d > 0.0f) ? rsqrtf(d) : 0.0f;
    int c = cnt[i];
    int b = min(c, NBINS - 1);
    atomicAdd(&dbins[b], 1);
    atomicAdd(&ebins[b], c);
}

// exclusive scans of node counts and edge counts (64 entries each)
__global__ void bin_scan_kernel(const int* __restrict__ dbins, const int* __restrict__ ebins,
                                int* __restrict__ dcur, int* __restrict__ ecur) {
    __shared__ int sn[NBINS];
    __shared__ int se[NBINS];
    int t = threadIdx.x;
    int vn = dbins[t];
    int ve = ebins[t];
    sn[t] = vn;
    se[t] = ve;
    __syncthreads();
#pragma unroll
    for (int off = 1; off < NBINS; off <<= 1) {
        int tn = (t >= off) ? sn[t - off] : 0;
        int te = (t >= off) ? se[t - off] : 0;
        __syncthreads();
        sn[t] += tn;
        se[t] += te;
        __syncthreads();
    }
    dcur[t] = sn[t] - vn;
    ecur[t] = se[t] - ve;
}

// scatter nodes into degree order + assign CSR row ranges directly (no global scan)
__global__ __launch_bounds__(256)
void bin_scatter_kernel(const int* __restrict__ cnt,
                        int* __restrict__ dcur, int* __restrict__ ecur,
                        int* __restrict__ perm, int* __restrict__ rank,
                        int* __restrict__ rowstart, int* __restrict__ rowlen,
                        int* __restrict__ cursor) {
    int i = blockIdx.x * blockDim.x + threadIdx.x;
    if (i >= NN) return;
    int c = cnt[i];
    int b = min(c, NBINS - 1);
    int npos = atomicAdd(&dcur[b], 1);
    int epos = atomicAdd(&ecur[b], c);
    perm[npos] = i;
    rank[i] = npos;
    rowstart[npos] = epos;
    rowlen[npos] = c;
    cursor[npos] = epos;
}

__global__ void permute_x_kernel(const float* __restrict__ x, const int* __restrict__ perm,
                                 float* __restrict__ xp) {
    unsigned tid = blockIdx.x * blockDim.x + threadIdx.x;
    unsigned g = tid >> 4;
    if (g >= NN) return;
    unsigned lane = tid & 15u;
    int n = perm[g];
    reinterpret_cast<float4*>(xp)[(size_t)g * 16 + lane] =
        reinterpret_cast<const float4*>(x)[(size_t)n * 16 + lane];
}

__global__ void scatter_kernel(const int* __restrict__ src, const int* __restrict__ dst,
                               const float* __restrict__ w, const float* __restrict__ dinv,
                               const int* __restrict__ rank,
                               int* __restrict__ cursor, float2* __restrict__ adj) {
    int e = blockIdx.x * blockDim.x + threadIdx.x;
    if (e >= EE) return;
    int s = src[e], d = dst[e];
    float ww = (s == d) ? 0.0f : w[e];
    float nrm = -dinv[s] * ww * dinv[d];
    int pos = atomicAdd(&cursor[rank[d]], 1);
    adj[pos] = make_float2(__int_as_float(rank[s]), nrm);
}

// W conversion: per slice, hi[n][kk] then lo[n][kk] (bf16). B[n][kk] = W[kk][n].
__global__ void convw_kernel(const float* __restrict__ Wt, __nv_bfloat16* __restrict__ Wc) {
    int idx = blockIdx.x * blockDim.x + threadIdx.x;
    if (idx >= LL * KK * DD * DD) return;
    int n = idx & 63;
    int kk = (idx >> 6) & 63;
    int slice = idx >> 12;
    float w = Wt[(size_t)slice * 4096 + kk * 64 + n];
    __nv_bfloat16 hi = __float2bfloat16(w);
    __nv_bfloat16 lo = __float2bfloat16(w - __bfloat162float(hi));
    __nv_bfloat16* base = Wc + (size_t)slice * 8192;
    base[n * 64 + kk] = hi;
    base[4096 + n * 64 + kk] = lo;
}

// ---------------- CSR gather propagation (r12-proven loop; (start,len) rows) ----------------
#define EDGE_FMA(p, v) do { \
    acc.x = fmaf((p).y, (v).x, acc.x); acc.y = fmaf((p).y, (v).y, acc.y); \
    acc.z = fmaf((p).y, (v).z, acc.z); acc.w = fmaf((p).y, (v).w, acc.w); \
} while (0)

template <bool FIRST>
__global__ __launch_bounds__(256)
void prop16_kernel(const float* __restrict__ h, const float2* __restrict__ adj,
                   const int* __restrict__ rowstart, const int* __restrict__ rowlen,
                   const float* __restrict__ t0, float* __restrict__ out) {
    unsigned tid = blockIdx.x * blockDim.x + threadIdx.x;
    unsigned n = tid >> 4;
    if (n >= NN) return;
    unsigned lane = tid & 15u;
    int r0 = rowstart[n];
    int r1 = r0 + rowlen[n];

    float4 acc = make_float4(0.f, 0.f, 0.f, 0.f);
    const float4* hb = reinterpret_cast<const float4*>(h);

    int e = r0;
#pragma unroll 1
    for (; e + 7 < r1; e += 8) {
        float2 p0 = __ldg(&adj[e]);
        float2 p1 = __ldg(&adj[e + 1]);
        float2 p2 = __ldg(&adj[e + 2]);
        float2 p3 = __ldg(&adj[e + 3]);
        float2 p4 = __ldg(&adj[e + 4]);
        float2 p5 = __ldg(&adj[e + 5]);
        float2 p6 = __ldg(&adj[e + 6]);
        float2 p7 = __ldg(&adj[e + 7]);
        float4 v0 = hb[(size_t)__float_as_int(p0.x) * 16 + lane];
        float4 v1 = hb[(size_t)__float_as_int(p1.x) * 16 + lane];
        float4 v2 = hb[(size_t)__float_as_int(p2.x) * 16 + lane];
        float4 v3 = hb[(size_t)__float_as_int(p3.x) * 16 + lane];
        float4 v4 = hb[(size_t)__float_as_int(p4.x) * 16 + lane];
        float4 v5 = hb[(size_t)__float_as_int(p5.x) * 16 + lane];
        float4 v6 = hb[(size_t)__float_as_int(p6.x) * 16 + lane];
        float4 v7 = hb[(size_t)__float_as_int(p7.x) * 16 + lane];
        EDGE_FMA(p0, v0); EDGE_FMA(p1, v1); EDGE_FMA(p2, v2); EDGE_FMA(p3, v3);
        EDGE_FMA(p4, v4); EDGE_FMA(p5, v5); EDGE_FMA(p6, v6); EDGE_FMA(p7, v7);
    }
#pragma unroll 1
    for (; e + 3 < r1; e += 4) {
        float2 p0 = __ldg(&adj[e]);
        float2 p1 = __ldg(&adj[e + 1]);
        float2 p2 = __ldg(&adj[e + 2]);
        float2 p3 = __ldg(&adj[e + 3]);
        float4 v0 = hb[(size_t)__float_as_int(p0.x) * 16 + lane];
        float4 v1 = hb[(size_t)__float_as_int(p1.x) * 16 + lane];
        float4 v2 = hb[(size_t)__float_as_int(p2.x) * 16 + lane];
        float4 v3 = hb[(size_t)__float_as_int(p3.x) * 16 + lane];
        EDGE_FMA(p0, v0); EDGE_FMA(p1, v1); EDGE_FMA(p2, v2); EDGE_FMA(p3, v3);
    }
#pragma unroll 1
    for (; e < r1; e++) {
        float2 p0 = __ldg(&adj[e]);
        float4 v0 = hb[(size_t)__float_as_int(p0.x) * 16 + lane];
        EDGE_FMA(p0, v0);
    }

    size_t idx = (size_t)n * 16 + lane;
    if (FIRST) {
        reinterpret_cast<float4*>(out)[idx] = acc;
    } else {
        float4 t = reinterpret_cast<const float4*>(t0)[idx];
        reinterpret_cast<float4*>(out)[idx] =
            make_float4(2.0f * acc.x - t.x, 2.0f * acc.y - t.y,
                        2.0f * acc.z - t.z, 2.0f * acc.w - t.w);
    }
}

// ---------------- mma.sync bf16 hi/lo-split GEMM + bias + relu (r11-proven) ----------------
struct TPtrs { const float* p[KK]; };

#define PADROW 144               // 72 bf16 = 144 bytes per smem row
#define SM_XHI  0                // [128][72] bf16
#define SM_XLO  18432
#define SM_WHI  36864            // [64][72] bf16
#define SM_WLO  46080
#define SM_TOTAL 55296

#define MMA_BF16(c, a0, a1, a2, a3, b0, b1) \
    asm volatile("mma.sync.aligned.m16n8k16.row.col.f32.bf16.bf16.f32 " \
                 "{%0,%1,%2,%3}, {%4,%5,%6,%7}, {%8,%9}, {%0,%1,%2,%3};" \
                 : "+f"((c)[0]), "+f"((c)[1]), "+f"((c)[2]), "+f"((c)[3]) \
                 : "r"(a0), "r"(a1), "r"(a2), "r"(a3), "r"(b0), "r"(b1))

__global__ __launch_bounds__(256)
void gemm_mma_kernel(TPtrs ts, const __nv_bfloat16* __restrict__ Wc_layer,
                     const float* __restrict__ bias, float* __restrict__ out,
                     const int* __restrict__ operm) {
    extern __shared__ __align__(16) char smem[];
    int tid = threadIdx.x;
    int w = tid >> 5;
    int lane = tid & 31;
    int gid = lane >> 2;
    int tig = lane & 3;
    int row0 = blockIdx.x * 128;
    int rA = w * 16 + gid;

    float acc[8][4];
#pragma unroll
    for (int nt = 0; nt < 8; nt++)
#pragma unroll
        for (int c = 0; c < 4; c++) acc[nt][c] = 0.0f;

    for (int s = 0; s < KK; ++s) {
        if (s > 0) __syncthreads();

        const float4* Xv = reinterpret_cast<const float4*>(ts.p[s]);
#pragma unroll
        for (int i = 0; i < 8; i++) {
            int idx = tid + i * 256;
            int r = idx >> 4, c4 = idx & 15;
            int gr = row0 + r;
            float4 v = make_float4(0.f, 0.f, 0.f, 0.f);
            if (gr < NN) v = Xv[(size_t)gr * 16 + c4];
            __nv_bfloat162 h01 = __floats2bfloat162_rn(v.x, v.y);
            __nv_bfloat162 h23 = __floats2bfloat162_rn(v.z, v.w);
            float2 f01 = __bfloat1622float2(h01);
            float2 f23 = __bfloat1622float2(h23);
            __nv_bfloat162 l01 = __floats2bfloat162_rn(v.x - f01.x, v.y - f01.y);
            __nv_bfloat162 l23 = __floats2bfloat162_rn(v.z - f23.x, v.w - f23.y);
            uint32_t off = (uint32_t)r * PADROW + (uint32_t)c4 * 8;
            *reinterpret_cast<__nv_bfloat162*>(smem + SM_XHI + off) = h01;
            *reinterpret_cast<__nv_bfloat162*>(smem + SM_XHI + off + 4) = h23;
            *reinterpret_cast<__nv_bfloat162*>(smem + SM_XLO + off) = l01;
            *reinterpret_cast<__nv_bfloat162*>(smem + SM_XLO + off + 4) = l23;
        }
        const uint2* Wg = reinterpret_cast<const uint2*>(Wc_layer) + (size_t)s * 2048;
#pragma unroll
        for (int i = 0; i < 8; i++) {
            int idx = tid + i * 256;
            int half = idx >> 10;
            int j = idx & 1023;
            int n = j >> 4, c = j & 15;
            uint2 val = Wg[idx];
            *reinterpret_cast<uint2*>(smem + (half ? SM_WLO : SM_WHI)
                                      + (uint32_t)n * PADROW + (uint32_t)c * 8) = val;
        }
        __syncthreads();

#pragma unroll
        for (int kstep = 0; kstep < 4; kstep++) {
            uint32_t acol = (uint32_t)(kstep * 16 + 2 * tig) * 2;
            const char* axh = smem + SM_XHI + (uint32_t)rA * PADROW + acol;
            const char* axl = smem + SM_XLO + (uint32_t)rA * PADROW + acol;
            uint32_t ah0 = *reinterpret_cast<const uint32_t*>(axh);
            uint32_t ah1 = *reinterpret_cast<const uint32_t*>(axh + 8 * PADROW);
            uint32_t ah2 = *reinterpret_cast<const uint32_t*>(axh + 16);
            uint32_t ah3 = *reinterpret_cast<const uint32_t*>(axh + 8 * PADROW + 16);
            uint32_t al0 = *reinterpret_cast<const uint32_t*>(axl);
            uint32_t al1 = *reinterpret_cast<const uint32_t*>(axl + 8 * PADROW);
            uint32_t al2 = *reinterpret_cast<const uint32_t*>(axl + 16);
            uint32_t al3 = *reinterpret_cast<const uint32_t*>(axl + 8 * PADROW + 16);
#pragma unroll
            for (int nt = 0; nt < 8; nt++) {
                uint32_t boff = (uint32_t)(nt * 8 + gid) * PADROW + acol;
                uint32_t bh0 = *reinterpret_cast<const uint32_t*>(smem + SM_WHI + boff);
                uint32_t bh1 = *reinterpret_cast<const uint32_t*>(smem + SM_WHI + boff + 16);
                uint32_t bl0 = *reinterpret_cast<const uint32_t*>(smem + SM_WLO + boff);
                uint32_t bl1 = *reinterpret_cast<const uint32_t*>(smem + SM_WLO + boff + 16);
                MMA_BF16(acc[nt], ah0, ah1, ah2, ah3, bh0, bh1);
                MMA_BF16(acc[nt], al0, al1, al2, al3, bh0, bh1);
                MMA_BF16(acc[nt], ah0, ah1, ah2, ah3, bl0, bl1);
            }
        }
    }

    int gr1 = row0 + rA;
    int gr2 = gr1 + 8;
    int or1 = (gr1 < NN) ? (operm ? operm[gr1] : gr1) : -1;
    int or2 = (gr2 < NN) ? (operm ? operm[gr2] : gr2) : -1;
#pragma unroll
    for (int nt = 0; nt < 8; nt++) {
        int col = nt * 8 + 2 * tig;
        float b0 = bias[col], b1 = bias[col + 1];
        if (or1 >= 0) {
            float2 v;
            v.x = fmaxf(acc[nt][0] + b0, 0.f);
            v.y = fmaxf(acc[nt][1] + b1, 0.f);
            *reinterpret_cast<float2*>(out + (size_t)or1 * DD + col) = v;
        }
        if (or2 >= 0) {
            float2 v;
            v.x = fmaxf(acc[nt][2] + b0, 0.f);
            v.y = fmaxf(acc[nt][3] + b1, 0.f);
            *reinterpret_cast<float2*>(out + (size_t)or2 * DD + col) = v;
        }
    }
}

// ---------------- launcher ----------------
extern "C" void kernel_launch(void* const* d_in, const int* in_sizes, int n_in,
                              void* d_out, int out_size) {
    const float* x  = (const float*)d_in[0];
    const int*   ei = (const int*)d_in[1];
    const float* ew = (const float*)d_in[2];
    const float* Wt = (const float*)d_in[3];
    const float* Bs = (const float*)d_in[4];
    const int* src = ei;
    const int* dst = ei + EE;

    float *Tbuf, *out1, *out2, *xp, *deg, *dinv;
    int *cnt, *rowstart, *rowlen, *cursor, *dbins, *ebins, *dcur, *ecur, *perm, *rank;
    float2* adj;
    __nv_bfloat16* Wc;
    cudaGetSymbolAddress((void**)&Tbuf, g_T);
    cudaGetSymbolAddress((void**)&out1, g_out1);
    cudaGetSymbolAddress((void**)&out2, g_out2);
    cudaGetSymbolAddress((void**)&xp, g_xp);
    cudaGetSymbolAddress((void**)&deg, g_deg);
    cudaGetSymbolAddress((void**)&dinv, g_dinv);
    cudaGetSymbolAddress((void**)&cnt, g_cnt);
    cudaGetSymbolAddress((void**)&rowstart, g_rowstart);
    cudaGetSymbolAddress((void**)&rowlen, g_rowlen);
    cudaGetSymbolAddress((void**)&cursor, g_cursor);
    cudaGetSymbolAddress((void**)&dbins, g_dbins);
    cudaGetSymbolAddress((void**)&ebins, g_ebins);
    cudaGetSymbolAddress((void**)&dcur, g_dcur);
    cudaGetSymbolAddress((void**)&ecur, g_ecur);
    cudaGetSymbolAddress((void**)&perm, g_perm);
    cudaGetSymbolAddress((void**)&rank, g_rank);
    cudaGetSymbolAddress((void**)&adj, g_adj);
    cudaGetSymbolAddress((void**)&Wc, g_Wc);

    static int smem_set = 0;
    if (!smem_set) {
        cudaFuncSetAttribute(gemm_mma_kernel,
                             cudaFuncAttributeMaxDynamicSharedMemorySize, SM_TOTAL);
        smem_set = 1;
    }

    const size_t FB = (size_t)NN * DD;
    float* TB[7];
    for (int i = 0; i < 7; i++) TB[i] = Tbuf + (size_t)i * FB;

    const int T = 256;
    const int edgeBlocks = (EE + T - 1) / T;
    const int nodeBlocks = (NN + T - 1) / T;
    const int propBlocks = (NN * 16 + T - 1) / T;
    const int gemmBlocks = (NN + 127) / 128;
    const int convwBlocks = (LL * KK * DD * DD + T - 1) / T;

    // --- setup ---
    cudaMemsetAsync(deg, 0, NN * sizeof(float));
    cudaMemsetAsync(cnt, 0, NN * sizeof(int));
    cudaMemsetAsync(dbins, 0, NBINS * sizeof(int));
    cudaMemsetAsync(ebins, 0, NBINS * sizeof(int));
    deg_hist_kernel<<<edgeBlocks, T>>>(src, dst, ew, deg, cnt);
    dinv_binhist_kernel<<<nodeBlocks, T>>>(deg, cnt, dinv, dbins, ebins);
    bin_scan_kernel<<<1, NBINS>>>(dbins, ebins, dcur, ecur);
    bin_scatter_kernel<<<nodeBlocks, T>>>(cnt, dcur, ecur, perm, rank,
                                          rowstart, rowlen, cursor);
    scatter_kernel<<<edgeBlocks, T>>>(src, dst, ew, dinv, rank, cursor, adj);
    permute_x_kernel<<<propBlocks, T>>>(x, perm, xp);
    convw_kernel<<<convwBlocks, T>>>(Wt, Wc);

    // --- layers ---
    const float* hin = xp;
    float* houts[3] = {out1, out2, (float*)d_out};

    for (int l = 0; l < LL; l++) {
        prop16_kernel<true><<<propBlocks, T>>>(hin, adj, rowstart, rowlen, nullptr, TB[0]);
        for (int k = 2; k < KK; k++) {
            const float* tin = TB[k - 2];
            const float* t0 = (k == 2) ? hin : TB[k - 3];
            prop16_kernel<false><<<propBlocks, T>>>(tin, adj, rowstart, rowlen, t0, TB[k - 1]);
        }
        TPtrs tsp;
        tsp.p[0] = hin;
        for (int k = 1; k < KK; k++) tsp.p[k] = TB[k - 1];
        const int* operm = (l == LL - 1) ? perm : nullptr;
        gemm_mma_kernel<<<gemmBlocks, 256, SM_TOTAL>>>(
            tsp, Wc + (size_t)l * KK * 2 * DD * DD, Bs + (size_t)l * DD,
            houts[l], operm);
        hin = houts[l];
    }
}

// round 16
// speedup vs baseline: 1.2849x; 1.2113x over previous
#include <cuda_runtime.h>
#include <cuda_bf16.h>
#include <cstdint>
#include <cstddef>

#define NN 100000
#define EE 1000000
#define DD 64
#define KK 8
#define LL 3

#define SCAN_TPB 1024
#define SCAN_BLOCKS ((NN + SCAN_TPB - 1) / SCAN_TPB)   // 98
#define NBINS 64

// ---------------- device scratch ----------------
__device__ float g_T[7][(size_t)NN * DD];
__device__ float g_out1[(size_t)NN * DD];
__device__ float g_out2[(size_t)NN * DD];
__device__ float g_xp[(size_t)NN * DD];
__device__ float g_deg[NN];
__device__ float g_dinv[NN];
__device__ int   g_cnt[NN];
__device__ int   g_cntp[NN];
__device__ int   g_rowstart[NN + 1];
__device__ int   g_cursor[NN];
__device__ int   g_bsum[SCAN_BLOCKS + 32];
__device__ int   g_dbins[NBINS];
__device__ int   g_dcur[NBINS];
__device__ int   g_perm[NN];
__device__ int   g_rank[NN];
__device__ float2 g_adj[EE];
// W pre-converted per (l,k) slice: 4096 bf16 hi then 4096 bf16 lo, layout [n][kk].
__device__ __align__(16) __nv_bfloat16 g_Wc[LL * KK * 2 * DD * DD];

// ---------------- normalization / CSR / sort (r12-proven, unchanged) ----------------
__global__ void deg_hist_kernel(const int* __restrict__ src, const int* __restrict__ dst,
                                const float* __restrict__ w,
                                float* __restrict__ deg, int* __restrict__ cnt) {
    int e = blockIdx.x * blockDim.x + threadIdx.x;
    if (e >= EE) return;
    int s = src[e], d = dst[e];
    float ww = (s == d) ? 0.0f : w[e];
    if (ww != 0.0f) atomicAdd(&deg[s], ww);
    atomicAdd(&cnt[d], 1);
}

__global__ void dinv_binhist_kernel(const float* __restrict__ deg, const int* __restrict__ cnt,
                                    float* __restrict__ dinv, int* __restrict__ dbins) {
    int i = blockIdx.x * blockDim.x + threadIdx.x;
    if (i >= NN) return;
    float d = deg[i];
    dinv[i] = (d > 0.0f) ? rsqrtf(d) : 0.0f;
    atomicAdd(&dbins[min(cnt[i], NBINS - 1)], 1);
}

__global__ void bin_scan_kernel(const int* __restrict__ dbins, int* __restrict__ dcur) {
    __shared__ int s[NBINS];
    int t = threadIdx.x;
    int v = dbins[t];
    s[t] = v;
    __syncthreads();
#pragma unroll
    for (int off = 1; off < NBINS; off <<= 1) {
        int tt = (t >= off) ? s[t - off] : 0;
        __syncthreads();
        s[t] += tt;
        __syncthreads();
    }
    dcur[t] = s[t] - v;
}

// block-aggregated scatter: smem histogram, one global atomic per bin per block
__global__ __launch_bounds__(256)
void bin_scatter_kernel(const int* __restrict__ cnt, int* __restrict__ dcur,
                        int* __restrict__ perm, int* __restrict__ rank,
                        int* __restrict__ cntp) {
    __shared__ int localCnt[NBINS];
    __shared__ int localBase[NBINS];
    int tid = threadIdx.x;
    if (tid < NBINS) localCnt[tid] = 0;
    __syncthreads();
    int i = blockIdx.x * blockDim.x + tid;
    int c = 0, b = 0, lpos = 0;
    bool valid = (i < NN);
    if (valid) {
        c = cnt[i];
        b = min(c, NBINS - 1);
        lpos = atomicAdd(&localCnt[b], 1);
    }
    __syncthreads();
    if (tid < NBINS && localCnt[tid] > 0)
        localBase[tid] = atomicAdd(&dcur[tid], localCnt[tid]);
    __syncthreads();
    if (valid) {
        int pos = localBase[b] + lpos;
        perm[pos] = i;
        rank[i] = pos;
        cntp[pos] = c;
    }
}

__global__ void permute_x_kernel(const float* __restrict__ x, const int* __restrict__ perm,
                                 float* __restrict__ xp) {
    unsigned tid = blockIdx.x * blockDim.x + threadIdx.x;
    unsigned g = tid >> 4;
    if (g >= NN) return;
    unsigned lane = tid & 15u;
    int n = perm[g];
    reinterpret_cast<float4*>(xp)[(size_t)g * 16 + lane] =
        reinterpret_cast<const float4*>(x)[(size_t)n * 16 + lane];
}

__global__ void scan_block_kernel(const int* __restrict__ cnt, int* __restrict__ rowstart,
                                  int* __restrict__ bsum) {
    __shared__ int s[SCAN_TPB];
    int i = blockIdx.x * SCAN_TPB + threadIdx.x;
    int v = (i < NN) ? cnt[i] : 0;
    s[threadIdx.x] = v;
    __syncthreads();
#pragma unroll
    for (int off = 1; off < SCAN_TPB; off <<= 1) {
        int t = (threadIdx.x >= off) ? s[threadIdx.x - off] : 0;
        __syncthreads();
        s[threadIdx.x] += t;
        __syncthreads();
    }
    if (i <= NN) rowstart[i] = s[threadIdx.x] - v;
    if (threadIdx.x == SCAN_TPB - 1) bsum[blockIdx.x] = s[threadIdx.x];
}

__global__ void scan_sums_kernel(int* __restrict__ bsum) {
    __shared__ int s[128];
    int t = threadIdx.x;
    int v = (t < SCAN_BLOCKS) ? bsum[t] : 0;
    s[t] = v;
    __syncthreads();
#pragma unroll
    for (int off = 1; off < 128; off <<= 1) {
        int tt = (t >= off) ? s[t - off] : 0;
        __syncthreads();
        s[t] += tt;
        __syncthreads();
    }
    if (t < SCAN_BLOCKS) bsum[t] = s[t] - v;
}

__global__ void scan_add_kernel(int* __restrict__ rowstart, const int* __restrict__ bsum,
                                int* __restrict__ cursor) {
    int i = blockIdx.x * blockDim.x + threadIdx.x;
    if (i > NN) return;
    int r = rowstart[i] + bsum[i / SCAN_TPB];
    rowstart[i] = r;
    if (i < NN) cursor[i] = r;
}

__global__ void scatter_kernel(const int* __restrict__ src, const int* __restrict__ dst,
                               const float* __restrict__ w, const float* __restrict__ dinv,
                               const int* __restrict__ rank,
                               int* __restrict__ cursor, float2* __restrict__ adj) {
    int e = blockIdx.x * blockDim.x + threadIdx.x;
    if (e >= EE) return;
    int s = src[e], d = dst[e];
    float ww = (s == d) ? 0.0f : w[e];
    float nrm = -dinv[s] * ww * dinv[d];
    int pos = atomicAdd(&cursor[rank[d]], 1);
    adj[pos] = make_float2(__int_as_float(rank[s]), nrm);
}

// W conversion: per slice, hi[n][kk] then lo[n][kk] (bf16). B[n][kk] = W[kk][n].
__global__ void convw_kernel(const float* __restrict__ Wt, __nv_bfloat16* __restrict__ Wc) {
    int idx = blockIdx.x * blockDim.x + threadIdx.x;
    if (idx >= LL * KK * DD * DD) return;
    int n = idx & 63;
    int kk = (idx >> 6) & 63;
    int slice = idx >> 12;
    float w = Wt[(size_t)slice * 4096 + kk * 64 + n];
    __nv_bfloat16 hi = __float2bfloat16(w);
    __nv_bfloat16 lo = __float2bfloat16(w - __bfloat162float(hi));
    __nv_bfloat16* base = Wc + (size_t)slice * 8192;
    base[n * 64 + kk] = hi;
    base[4096 + n * 64 + kk] = lo;
}

// ---------------- CSR gather propagation (r12-proven, unchanged) ----------------
#define EDGE_FMA(p, v) do { \
    acc.x = fmaf((p).y, (v).x, acc.x); acc.y = fmaf((p).y, (v).y, acc.y); \
    acc.z = fmaf((p).y, (v).z, acc.z); acc.w = fmaf((p).y, (v).w, acc.w); \
} while (0)

template <bool FIRST>
__global__ __launch_bounds__(256)
void prop16_kernel(const float* __restrict__ h, const float2* __restrict__ adj,
                   const int* __restrict__ rowstart, const float* __restrict__ t0,
                   float* __restrict__ out) {
    unsigned tid = blockIdx.x * blockDim.x + threadIdx.x;
    unsigned n = tid >> 4;
    if (n >= NN) return;
    unsigned lane = tid & 15u;
    int r0 = rowstart[n];
    int r1 = rowstart[n + 1];

    float4 acc = make_float4(0.f, 0.f, 0.f, 0.f);
    const float4* hb = reinterpret_cast<const float4*>(h);

    int e = r0;
#pragma unroll 1
    for (; e + 7 < r1; e += 8) {
        float2 p0 = __ldg(&adj[e]);
        float2 p1 = __ldg(&adj[e + 1]);
        float2 p2 = __ldg(&adj[e + 2]);
        float2 p3 = __ldg(&adj[e + 3]);
        float2 p4 = __ldg(&adj[e + 4]);
        float2 p5 = __ldg(&adj[e + 5]);
        float2 p6 = __ldg(&adj[e + 6]);
        float2 p7 = __ldg(&adj[e + 7]);
        float4 v0 = hb[(size_t)__float_as_int(p0.x) * 16 + lane];
        float4 v1 = hb[(size_t)__float_as_int(p1.x) * 16 + lane];
        float4 v2 = hb[(size_t)__float_as_int(p2.x) * 16 + lane];
        float4 v3 = hb[(size_t)__float_as_int(p3.x) * 16 + lane];
        float4 v4 = hb[(size_t)__float_as_int(p4.x) * 16 + lane];
        float4 v5 = hb[(size_t)__float_as_int(p5.x) * 16 + lane];
        float4 v6 = hb[(size_t)__float_as_int(p6.x) * 16 + lane];
        float4 v7 = hb[(size_t)__float_as_int(p7.x) * 16 + lane];
        EDGE_FMA(p0, v0); EDGE_FMA(p1, v1); EDGE_FMA(p2, v2); EDGE_FMA(p3, v3);
        EDGE_FMA(p4, v4); EDGE_FMA(p5, v5); EDGE_FMA(p6, v6); EDGE_FMA(p7, v7);
    }
#pragma unroll 1
    for (; e + 3 < r1; e += 4) {
        float2 p0 = __ldg(&adj[e]);
        float2 p1 = __ldg(&adj[e + 1]);
        float2 p2 = __ldg(&adj[e + 2]);
        float2 p3 = __ldg(&adj[e + 3]);
        float4 v0 = hb[(size_t)__float_as_int(p0.x) * 16 + lane];
        float4 v1 = hb[(size_t)__float_as_int(p1.x) * 16 + lane];
        float4 v2 = hb[(size_t)__float_as_int(p2.x) * 16 + lane];
        float4 v3 = hb[(size_t)__float_as_int(p3.x) * 16 + lane];
        EDGE_FMA(p0, v0); EDGE_FMA(p1, v1); EDGE_FMA(p2, v2); EDGE_FMA(p3, v3);
    }
#pragma unroll 1
    for (; e < r1; e++) {
        float2 p0 = __ldg(&adj[e]);
        float4 v0 = hb[(size_t)__float_as_int(p0.x) * 16 + lane];
        EDGE_FMA(p0, v0);
    }

    size_t idx = (size_t)n * 16 + lane;
    if (FIRST) {
        reinterpret_cast<float4*>(out)[idx] = acc;
    } else {
        float4 t = reinterpret_cast<const float4*>(t0)[idx];
        reinterpret_cast<float4*>(out)[idx] =
            make_float4(2.0f * acc.x - t.x, 2.0f * acc.y - t.y,
                        2.0f * acc.z - t.z, 2.0f * acc.w - t.w);
    }
}

// ---------------- mma.sync bf16 hi/lo GEMM + bias + relu, register-prefetch pipelined ----------------
struct TPtrs { const float* p[KK]; };

#define PADROW 144               // 72 bf16 = 144 bytes per smem row
#define SM_XHI  0                // [128][72] bf16
#define SM_XLO  18432
#define SM_WHI  36864            // [64][72] bf16
#define SM_WLO  46080
#define SM_TOTAL 55296

#define MMA_BF16(c, a0, a1, a2, a3, b0, b1) \
    asm volatile("mma.sync.aligned.m16n8k16.row.col.f32.bf16.bf16.f32 " \
                 "{%0,%1,%2,%3}, {%4,%5,%6,%7}, {%8,%9}, {%0,%1,%2,%3};" \
                 : "+f"((c)[0]), "+f"((c)[1]), "+f"((c)[2]), "+f"((c)[3]) \
                 : "r"(a0), "r"(a1), "r"(a2), "r"(a3), "r"(b0), "r"(b1))

__global__ __launch_bounds__(256)
void gemm_mma_kernel(TPtrs ts, const __nv_bfloat16* __restrict__ Wc_layer,
                     const float* __restrict__ bias, float* __restrict__ out,
                     const int* __restrict__ operm) {
    extern __shared__ __align__(16) char smem[];
    int tid = threadIdx.x;
    int w = tid >> 5;
    int lane = tid & 31;
    int gid = lane >> 2;
    int tig = lane & 3;
    int row0 = blockIdx.x * 128;
    int rA = w * 16 + gid;

    float acc[8][4];
#pragma unroll
    for (int nt = 0; nt < 8; nt++)
#pragma unroll
        for (int c = 0; c < 4; c++) acc[nt][c] = 0.0f;

    float4 xa[8];        // prefetched X chunks for current slice
    uint2 wv[8];         // prefetched W chunks for current slice

    // preload slice 0
    {
        const float4* Xv = reinterpret_cast<const float4*>(ts.p[0]);
#pragma unroll
        for (int i = 0; i < 8; i++) {
            int idx = tid + i * 256;
            int r = idx >> 4, c4 = idx & 15;
            int gr = row0 + r;
            xa[i] = (gr < NN) ? Xv[(size_t)gr * 16 + c4] : make_float4(0.f, 0.f, 0.f, 0.f);
        }
        const uint2* Wg = reinterpret_cast<const uint2*>(Wc_layer);
#pragma unroll
        for (int i = 0; i < 8; i++) wv[i] = Wg[tid + i * 256];
    }

    for (int s = 0; s < KK; ++s) {
        if (s > 0) __syncthreads();   // all warps finished reading prev slice's smem

        // store prefetched X (convert to bf16 hi/lo) and W into smem
#pragma unroll
        for (int i = 0; i < 8; i++) {
            int idx = tid + i * 256;
            int r = idx >> 4, c4 = idx & 15;
            float4 v = xa[i];
            __nv_bfloat162 h01 = __floats2bfloat162_rn(v.x, v.y);
            __nv_bfloat162 h23 = __floats2bfloat162_rn(v.z, v.w);
            float2 f01 = __bfloat1622float2(h01);
            float2 f23 = __bfloat1622float2(h23);
            __nv_bfloat162 l01 = __floats2bfloat162_rn(v.x - f01.x, v.y - f01.y);
            __nv_bfloat162 l23 = __floats2bfloat162_rn(v.z - f23.x, v.w - f23.y);
            uint32_t off = (uint32_t)r * PADROW + (uint32_t)c4 * 8;
            *reinterpret_cast<__nv_bfloat162*>(smem + SM_XHI + off) = h01;
            *reinterpret_cast<__nv_bfloat162*>(smem + SM_XHI + off + 4) = h23;
            *reinterpret_cast<__nv_bfloat162*>(smem + SM_XLO + off) = l01;
            *reinterpret_cast<__nv_bfloat162*>(smem + SM_XLO + off + 4) = l23;
        }
#pragma unroll
        for (int i = 0; i < 8; i++) {
            int idx = tid + i * 256;
            int half = idx >> 10;
            int j = idx & 1023;
            int n = j >> 4, c = j & 15;
            *reinterpret_cast<uint2*>(smem + (half ? SM_WLO : SM_WHI)
                                      + (uint32_t)n * PADROW + (uint32_t)c * 8) = wv[i];
        }
        __syncthreads();

        // prefetch next slice while this slice's MMAs run
        if (s + 1 < KK) {
            const float4* Xv = reinterpret_cast<const float4*>(ts.p[s + 1]);
#pragma unroll
            for (int i = 0; i < 8; i++) {
                int idx = tid + i * 256;
                int r = idx >> 4, c4 = idx & 15;
                int gr = row0 + r;
                xa[i] = (gr < NN) ? Xv[(size_t)gr * 16 + c4] : make_float4(0.f, 0.f, 0.f, 0.f);
            }
            const uint2* Wg = reinterpret_cast<const uint2*>(Wc_layer) + (size_t)(s + 1) * 2048;
#pragma unroll
            for (int i = 0; i < 8; i++) wv[i] = Wg[tid + i * 256];
        }

        // compute
#pragma unroll
        for (int kstep = 0; kstep < 4; kstep++) {
            uint32_t acol = (uint32_t)(kstep * 16 + 2 * tig) * 2;
            const char* axh = smem + SM_XHI + (uint32_t)rA * PADROW + acol;
            const char* axl = smem + SM_XLO + (uint32_t)rA * PADROW + acol;
            uint32_t ah0 = *reinterpret_cast<const uint32_t*>(axh);
            uint32_t ah1 = *reinterpret_cast<const uint32_t*>(axh + 8 * PADROW);
            uint32_t ah2 = *reinterpret_cast<const uint32_t*>(axh + 16);
            uint32_t ah3 = *reinterpret_cast<const uint32_t*>(axh + 8 * PADROW + 16);
            uint32_t al0 = *reinterpret_cast<const uint32_t*>(axl);
            uint32_t al1 = *reinterpret_cast<const uint32_t*>(axl + 8 * PADROW);
            uint32_t al2 = *reinterpret_cast<const uint32_t*>(axl + 16);
            uint32_t al3 = *reinterpret_cast<const uint32_t*>(axl + 8 * PADROW + 16);
#pragma unroll
            for (int nt = 0; nt < 8; nt++) {
                uint32_t boff = (uint32_t)(nt * 8 + gid) * PADROW + acol;
                uint32_t bh0 = *reinterpret_cast<const uint32_t*>(smem + SM_WHI + boff);
                uint32_t bh1 = *reinterpret_cast<const uint32_t*>(smem + SM_WHI + boff + 16);
                uint32_t bl0 = *reinterpret_cast<const uint32_t*>(smem + SM_WLO + boff);
                uint32_t bl1 = *reinterpret_cast<const uint32_t*>(smem + SM_WLO + boff + 16);
                MMA_BF16(acc[nt], ah0, ah1, ah2, ah3, bh0, bh1);
                MMA_BF16(acc[nt], al0, al1, al2, al3, bh0, bh1);
                MMA_BF16(acc[nt], ah0, ah1, ah2, ah3, bl0, bl1);
            }
        }
    }

    int gr1 = row0 + rA;
    int gr2 = gr1 + 8;
    int or1 = (gr1 < NN) ? (operm ? operm[gr1] : gr1) : -1;
    int or2 = (gr2 < NN) ? (operm ? operm[gr2] : gr2) : -1;
#pragma unroll
    for (int nt = 0; nt < 8; nt++) {
        int col = nt * 8 + 2 * tig;
        float b0 = bias[col], b1 = bias[col + 1];
        if (or1 >= 0) {
            float2 v;
            v.x = fmaxf(acc[nt][0] + b0, 0.f);
            v.y = fmaxf(acc[nt][1] + b1, 0.f);
            *reinterpret_cast<float2*>(out + (size_t)or1 * DD + col) = v;
        }
        if (or2 >= 0) {
            float2 v;
            v.x = fmaxf(acc[nt][2] + b0, 0.f);
            v.y = fmaxf(acc[nt][3] + b1, 0.f);
            *reinterpret_cast<float2*>(out + (size_t)or2 * DD + col) = v;
        }
    }
}

// ---------------- launcher ----------------
extern "C" void kernel_launch(void* const* d_in, const int* in_sizes, int n_in,
                              void* d_out, int out_size) {
    const float* x  = (const float*)d_in[0];
    const int*   ei = (const int*)d_in[1];
    const float* ew = (const float*)d_in[2];
    const float* Wt = (const float*)d_in[3];
    const float* Bs = (const float*)d_in[4];
    const int* src = ei;
    const int* dst = ei + EE;

    float *Tbuf, *out1, *out2, *xp, *deg, *dinv;
    int *cnt, *cntp, *rowstart, *cursor, *bsum, *dbins, *dcur, *perm, *rank;
    float2* adj;
    __nv_bfloat16* Wc;
    cudaGetSymbolAddress((void**)&Tbuf, g_T);
    cudaGetSymbolAddress((void**)&out1, g_out1);
    cudaGetSymbolAddress((void**)&out2, g_out2);
    cudaGetSymbolAddress((void**)&xp, g_xp);
    cudaGetSymbolAddress((void**)&deg, g_deg);
    cudaGetSymbolAddress((void**)&dinv, g_dinv);
    cudaGetSymbolAddress((void**)&cnt, g_cnt);
    cudaGetSymbolAddress((void**)&cntp, g_cntp);
    cudaGetSymbolAddress((void**)&rowstart, g_rowstart);
    cudaGetSymbolAddress((void**)&cursor, g_cursor);
    cudaGetSymbolAddress((void**)&bsum, g_bsum);
    cudaGetSymbolAddress((void**)&dbins, g_dbins);
    cudaGetSymbolAddress((void**)&dcur, g_dcur);
    cudaGetSymbolAddress((void**)&perm, g_perm);
    cudaGetSymbolAddress((void**)&rank, g_rank);
    cudaGetSymbolAddress((void**)&adj, g_adj);
    cudaGetSymbolAddress((void**)&Wc, g_Wc);

    static int smem_set = 0;
    if (!smem_set) {
        cudaFuncSetAttribute(gemm_mma_kernel,
                             cudaFuncAttributeMaxDynamicSharedMemorySize, SM_TOTAL);
        smem_set = 1;
    }

    const size_t FB = (size_t)NN * DD;
    float* TB[7];
    for (int i = 0; i < 7; i++) TB[i] = Tbuf + (size_t)i * FB;

    const int T = 256;
    const int edgeBlocks = (EE + T - 1) / T;
    const int nodeBlocks = (NN + T - 1) / T;
    const int node1Blocks = (NN + 1 + T - 1) / T;
    const int propBlocks = (NN * 16 + T - 1) / T;
    const int gemmBlocks = (NN + 127) / 128;
    const int convwBlocks = (LL * KK * DD * DD + T - 1) / T;

    // --- setup ---
    cudaMemsetAsync(deg, 0, NN * sizeof(float));
    cudaMemsetAsync(cnt, 0, NN * sizeof(int));
    cudaMemsetAsync(dbins, 0, NBINS * sizeof(int));
    deg_hist_kernel<<<edgeBlocks, T>>>(src, dst, ew, deg, cnt);
    dinv_binhist_kernel<<<nodeBlocks, T>>>(deg, cnt, dinv, dbins);
    bin_scan_kernel<<<1, NBINS>>>(dbins, dcur);
    bin_scatter_kernel<<<nodeBlocks, T>>>(cnt, dcur, perm, rank, cntp);
    scan_block_kernel<<<SCAN_BLOCKS, SCAN_TPB>>>(cntp, rowstart, bsum);
    scan_sums_kernel<<<1, 128>>>(bsum);
    scan_add_kernel<<<node1Blocks, T>>>(rowstart, bsum, cursor);
    scatter_kernel<<<edgeBlocks, T>>>(src, dst, ew, dinv, rank, cursor, adj);
    permute_x_kernel<<<propBlocks, T>>>(x, perm, xp);
    convw_kernel<<<convwBlocks, T>>>(Wt, Wc);

    // --- layers ---
    const float* hin = xp;
    float* houts[3] = {out1, out2, (float*)d_out};

    for (int l = 0; l < LL; l++) {
        prop16_kernel<true><<<propBlocks, T>>>(hin, adj, rowstart, nullptr, TB[0]);
        for (int k = 2; k < KK; k++) {
            const float* tin = TB[k - 2];
            const float* t0 = (k == 2) ? hin : TB[k - 3];
            prop16_kernel<false><<<propBlocks, T>>>(tin, adj, rowstart, t0, TB[k - 1]);
        }
        TPtrs tsp;
        tsp.p[0] = hin;
        for (int k = 1; k < KK; k++) tsp.p[k] = TB[k - 1];
        const int* operm = (l == LL - 1) ? perm : nullptr;
        gemm_mma_kernel<<<gemmBlocks, 256, SM_TOTAL>>>(
            tsp, Wc + (size_t)l * KK * 2 * DD * DD, Bs + (size_t)l * DD,
            houts[l], operm);
        hin = houts[l];
    }
}